// round 14
// baseline (speedup 1.0000x reference)
// Generator_causal on GB300 (compute_103 baseline): warp-level FP8 e4m3 mma.sync +
// ldmatrix. CTA = 256 threads = ONE 128-row batch tile (8 warps = 4 warp pairs).
// R14: B-fragment SOFTWARE PIPELINING inside each fused GEMM (ldsm for block nj+1
// issued before the epilogue stores of block nj) + first B-block of GEMM2/GEMM3
// preloaded BEFORE the preceding pair barrier (weights are read-only). Otherwise
// identical to R13: fused GEMM+epilogue per 16-col block, padded-stride linear
// layouts, adjacency mask folded into Wi offline, C-zero first-kstep mma,
// pair-local barriers, one CTA sync per step, 2 CTAs/SM.
// Scales: state=fp8(v); WiM=fp8(128*Wi*M); Ws=fp8(16*Ws); h=fp8(16*h).
#include <cuda_runtime.h>
#include <cuda_bf16.h>
#include <cstdint>

#define NTH    256
#define TILE_M 128

// device scratch: pre-packed fp8(128*Wi*Mcol) tiles (80B row stride) + z-col wts
__device__ __align__(16) uint8_t g_wi8[64][10240];
__device__ float g_wic16[64][128];

// ---------------- SMEM map (bytes) ----------------
#define OFF_STATE  1024u      // 128 rows x 80B = 10240
#define OFF_ACT1   11264u     // h1: 128 x 144B = 18432
#define OFF_ACT2   29696u     // h2: 128 x 144B = 18432
#define OFF_WIB    48128u     // 2 bufs x (128 x 80B) = 20480
#define OFF_WS1    68608u     // 128 x 144B = 18432
#define OFF_WS2    87040u     // 18432
#define OFF_VEC    105472u    // wic[2][128]|wfs[2][128]|bis[2][128]|bs1|bs2|part
#define SMEM_TOTAL 110080u

// ---------------- helpers ----------------
__device__ __forceinline__ uint32_t smem_u32(const void* p) {
    uint32_t a;
    asm("{ .reg .u64 t; cvta.to.shared.u64 t, %1; cvt.u32.u64 %0, t; }" : "=r"(a) : "l"(p));
    return a;
}
__device__ __forceinline__ uint16_t pk2_e4m3(float lo, float hi) {
    uint16_t r;
    asm("cvt.rn.satfinite.e4m3x2.f32 %0, %1, %2;" : "=h"(r) : "f"(hi), "f"(lo));
    return r;
}
__device__ __forceinline__ uint32_t pk4_e4m3(float v0, float v1, float v2, float v3) {
    uint16_t lo = pk2_e4m3(v0, v1), hi = pk2_e4m3(v2, v3);
    uint32_t r;
    asm("mov.b32 %0, {%1, %2};" : "=r"(r) : "h"(lo), "h"(hi));
    return r;
}
__device__ __forceinline__ uint8_t fp8b(float v) { return (uint8_t)pk2_e4m3(v, 0.f); }
__device__ __forceinline__ void sts32(uint32_t addr, uint32_t v) {
    asm volatile("st.shared.b32 [%0], %1;" :: "r"(addr), "r"(v) : "memory");
}
__device__ __forceinline__ void sts_b16(uint32_t addr, uint16_t v) {
    asm volatile("st.shared.b16 [%0], %1;" :: "r"(addr), "h"(v) : "memory");
}
__device__ __forceinline__ void sts_b8(uint32_t addr, uint32_t v) {
    asm volatile("st.shared.u8 [%0], %1;" :: "r"(addr), "r"(v) : "memory");
}
__device__ __forceinline__ void sts128(uint32_t addr, uint4 v) {
    asm volatile("st.shared.v4.b32 [%0], {%1,%2,%3,%4};"
                 :: "r"(addr), "r"(v.x), "r"(v.y), "r"(v.z), "r"(v.w) : "memory");
}
__device__ __forceinline__ void ldsm4(uint32_t addr, uint32_t* r) {
    asm volatile("ldmatrix.sync.aligned.m8n8.x4.shared.b16 {%0,%1,%2,%3}, [%4];"
                 : "=r"(r[0]), "=r"(r[1]), "=r"(r[2]), "=r"(r[3]) : "r"(addr));
}
__device__ __forceinline__ void mma_fp8(float* c, const uint32_t* a, uint32_t b0, uint32_t b1) {
    asm volatile("mma.sync.aligned.m16n8k32.row.col.f32.e4m3.e4m3.f32 "
                 "{%0,%1,%2,%3}, {%4,%5,%6,%7}, {%8,%9}, {%0,%1,%2,%3};"
                 : "+f"(c[0]), "+f"(c[1]), "+f"(c[2]), "+f"(c[3])
                 : "r"(a[0]), "r"(a[1]), "r"(a[2]), "r"(a[3]), "r"(b0), "r"(b1));
}
__device__ __forceinline__ void mma_fp8_z(float* d, const uint32_t* a, uint32_t b0, uint32_t b1) {
    asm volatile("mma.sync.aligned.m16n8k32.row.col.f32.e4m3.e4m3.f32 "
                 "{%0,%1,%2,%3}, {%4,%5,%6,%7}, {%8,%9}, {%10,%11,%12,%13};"
                 : "=f"(d[0]), "=f"(d[1]), "=f"(d[2]), "=f"(d[3])
                 : "r"(a[0]), "r"(a[1]), "r"(a[2]), "r"(a[3]), "r"(b0), "r"(b1),
                   "f"(0.f), "f"(0.f), "f"(0.f), "f"(0.f));
}
#define PAIRBAR(id) asm volatile("bar.sync %0, 64;" :: "r"(id) : "memory")

// prologue: fold adjacency column into Wi -> fp8(128 * Wi * M[k][s]), 80B rows
__global__ void prep_wi_kernel(const float* __restrict__ Wi, const float* __restrict__ Mg) {
    const int s = blockIdx.x;
    const float* src = Wi + (size_t)s * 8320;
    for (int idx = threadIdx.x; idx < 8320; idx += 256) {
        int n = idx / 65, k = idx - n * 65;
        float v = __ldg(src + idx);
        if (k < 64) g_wi8[s][n * 80 + k] = fp8b(128.f * v * __ldg(Mg + k * 64 + s));
        else        g_wic16[s][n] = 16.f * v;
    }
}

__global__ void __launch_bounds__(NTH, 2)
gen_causal_kernel(const float* __restrict__ x,   const float* __restrict__ z,
                  const float* __restrict__ bi,  const float* __restrict__ Ws1,
                  const float* __restrict__ bs1, const float* __restrict__ Ws2,
                  const float* __restrict__ bs2, const float* __restrict__ wf,
                  const float* __restrict__ bf,  float* __restrict__ out)
{
    extern __shared__ char smem[];
    const int tid  = threadIdx.x;
    const int lane = tid & 31;
    const int w    = tid >> 5;
    const int pair = w >> 1;                    // 0..3
    const int mrow0 = pair << 5;                // pair's 32 rows
    const int nhalf = w & 1;
    const int ncol0 = nhalf << 6;               // warp's 64 cols
    const int pid   = 1 + pair;
    const int grp   = lane >> 2, qd = lane & 3;
    const int lr = lane & 7, lt = (lane >> 3) & 1, lh = lane >> 4;
    const int tb    = blockIdx.x * TILE_M;
    const uint32_t sb     = smem_u32(smem);
    const uint32_t stateT = sb + OFF_STATE;     // 80B rows
    const uint32_t act1   = sb + OFF_ACT1;      // 144B rows
    const uint32_t act2   = sb + OFF_ACT2;      // 144B rows
    const uint32_t ws1T   = sb + OFF_WS1;
    const uint32_t ws2T   = sb + OFF_WS2;

    float* wicV = reinterpret_cast<float*>(smem + OFF_VEC);   // [2][128]
    float* wfsV = wicV + 256;                                 // [2][128]
    float* bisV = wfsV + 256;                                 // [2][128] (16*bi)
    float* bs1s = bisV + 256;                                 // [128] (16*bs1)
    float* bs2s = bs1s + 128;                                 // [128]
    float* partT = bs2s + 128;                                // [128]
    const float2* wic2a = reinterpret_cast<const float2*>(wicV);
    const float2* wfs2a = reinterpret_cast<const float2*>(wfsV);
    const float2* bis2a = reinterpret_cast<const float2*>(bisV);
    const float2* bs12  = reinterpret_cast<const float2*>(bs1s);
    const float2* bs22  = reinterpret_cast<const float2*>(bs2s);

    // ---- one-time init ----
    #pragma unroll 4
    for (int it = 0; it < 16; it++) {           // Ws1/Ws2 -> fp8(16*w), 144B rows
        int q = it * NTH + tid;
        int n = q >> 5, k4 = (q & 31) * 4;
        float4 a = __ldg(reinterpret_cast<const float4*>(Ws1) + q);
        float4 b = __ldg(reinterpret_cast<const float4*>(Ws2) + q);
        uint32_t o = (uint32_t)(n * 144 + k4);
        sts32(ws1T + o, pk4_e4m3(16.f * a.x, 16.f * a.y, 16.f * a.z, 16.f * a.w));
        sts32(ws2T + o, pk4_e4m3(16.f * b.x, 16.f * b.y, 16.f * b.z, 16.f * b.w));
    }
    #pragma unroll 4
    for (int it = 0; it < 8; it++) {            // state <- fp8(x), 80B rows
        int q = it * NTH + tid;
        int r = q >> 4, c4 = (q & 15) << 2;
        float4 v = __ldg(reinterpret_cast<const float4*>(x) + (size_t)blockIdx.x * 2048 + q);
        sts32(stateT + (uint32_t)(r * 80 + c4), pk4_e4m3(v.x, v.y, v.z, v.w));
    }
    #pragma unroll
    for (int it = 0; it < 3; it++) {            // Wi buffer 0 (640 uint4)
        int q = it * NTH + tid;
        if (q < 640) {
            int o = q * 16;
            sts128(sb + OFF_WIB + o, *reinterpret_cast<const uint4*>(g_wi8[0] + o));
        }
    }
    if (tid < 128) {
        wicV[tid] = g_wic16[0][tid];
        wfsV[tid] = __ldg(wf + tid);
        bisV[tid] = 16.f * __ldg(bi + tid);
        bs1s[tid] = 16.f * __ldg(bs1 + tid);
        bs2s[tid] = __ldg(bs2 + tid);
    }
    __syncthreads();

    const float* zbase = z + (size_t)(tb + mrow0 + grp) * 64;

    #pragma unroll 1
    for (int i = 0; i < 64; i++) {
        const int cur = i & 1, nxt = cur ^ 1;
        const float bfv = __ldg(bf + i);
        float zr[4];
        #pragma unroll
        for (int kq = 0; kq < 4; kq++)
            zr[kq] = __ldg(zbase + kq * 512 + i);

        // ========= GEMM1 + epi1 fused, B double-buffered (K=64, 80/80) =========
        {
            const uint32_t wib = sb + OFF_WIB + (uint32_t)cur * 10240u;
            uint32_t a1[2][2][4];                       // [ks][mt]
            #pragma unroll
            for (int mt = 0; mt < 2; mt++) {
                uint32_t ab = stateT + (uint32_t)((mrow0 + 16 * mt + lr + lt * 8) * 80)
                            + (uint32_t)(lh * 16);
                ldsm4(ab,       a1[0][mt]);
                ldsm4(ab + 32u, a1[1][mt]);
            }
            const uint32_t bb1 = wib + (uint32_t)((ncol0 + lr + lh * 8) * 80)
                               + (uint32_t)(lt * 16);   // +1280 per nj
            uint32_t bA[2][4], bB[2][4];                // [buf]
            ldsm4(bb1,       bA[0]);
            ldsm4(bb1 + 32u, bB[0]);
            const float2* wic2 = wic2a + cur * 64;
            const float2* bis2 = bis2a + cur * 64;
            #pragma unroll
            for (int nj = 0; nj < 4; nj++) {
                const int cb = nj & 1, nb = cb ^ 1;
                float acc[2][2][4];                     // [mt][sub]
                #pragma unroll
                for (int mt = 0; mt < 2; mt++) {
                    mma_fp8_z(acc[mt][0], a1[0][mt], bA[cb][0], bA[cb][1]);
                    mma_fp8_z(acc[mt][1], a1[0][mt], bA[cb][2], bA[cb][3]);
                    mma_fp8(acc[mt][0], a1[1][mt], bB[cb][0], bB[cb][1]);
                    mma_fp8(acc[mt][1], a1[1][mt], bB[cb][2], bB[cb][3]);
                }
                if (nj < 3) {                           // prefetch next B block
                    ldsm4(bb1 + (uint32_t)((nj + 1) * 1280),       bA[nb]);
                    ldsm4(bb1 + (uint32_t)((nj + 1) * 1280) + 32u, bB[nb]);
                }
                // epi1: h1_16 = relu(acc/8 + wic16*z + bi16) -> act1
                #pragma unroll
                for (int mt = 0; mt < 2; mt++) {
                    int rA = mrow0 + 16 * mt + grp;
                    float zA = zr[2 * mt], zB = zr[2 * mt + 1];
                    #pragma unroll
                    for (int sub = 0; sub < 2; sub++) {
                        int c = ncol0 + 16 * nj + 8 * sub + 2 * qd;
                        float2 wv = wic2[c >> 1];
                        float2 bv = bis2[c >> 1];
                        float* A = acc[mt][sub];
                        float v0 = fmaxf(fmaf(A[0], 0.125f, fmaf(wv.x, zA, bv.x)), 0.f);
                        float v1 = fmaxf(fmaf(A[1], 0.125f, fmaf(wv.y, zA, bv.y)), 0.f);
                        float v2 = fmaxf(fmaf(A[2], 0.125f, fmaf(wv.x, zB, bv.x)), 0.f);
                        float v3 = fmaxf(fmaf(A[3], 0.125f, fmaf(wv.y, zB, bv.y)), 0.f);
                        sts_b16(act1 + (uint32_t)(rA * 144 + c), pk2_e4m3(v0, v1));
                        sts_b16(act1 + (uint32_t)((rA + 8) * 144 + c), pk2_e4m3(v2, v3));
                    }
                }
            }
        }

        // ---- cooperative prefetch of step i+1 (sealed by boundary sync) ----
        if (i < 63) {
            const uint8_t* srcw = g_wi8[i + 1];
            const uint32_t dst = sb + OFF_WIB + (uint32_t)nxt * 10240u;
            #pragma unroll
            for (int it = 0; it < 3; it++) {
                int q = it * NTH + tid;
                if (q < 640) {
                    int o = q * 16;
                    sts128(dst + o, *reinterpret_cast<const uint4*>(srcw + o));
                }
            }
            if (tid < 128) {
                wicV[nxt * 128 + tid] = g_wic16[i + 1][tid];
                wfsV[nxt * 128 + tid] = __ldg(wf + (i + 1) * 128 + tid);
            } else {
                bisV[nxt * 128 + tid - 128] = 16.f * __ldg(bi + (i + 1) * 128 + tid - 128);
            }
        }

        // ---- preload GEMM2's first B block BEFORE the barrier (ws1 read-only) --
        const uint32_t bb2 = ws1T + (uint32_t)((ncol0 + lr + lh * 8) * 144)
                           + (uint32_t)(lt * 16);       // +2304 per nj
        uint32_t b2[2][4][4];                           // [buf][ks]
        #pragma unroll
        for (int ks = 0; ks < 4; ks++)
            ldsm4(bb2 + (uint32_t)(ks * 32), b2[0][ks]);
        PAIRBAR(pid);                                   // pair's h1 rows complete

        // ========= GEMM2 + epi2 fused, B double-buffered (K=128, 144/144) ======
        {
            uint32_t a2[4][2][4];                       // [ks][mt]
            #pragma unroll
            for (int mt = 0; mt < 2; mt++) {
                uint32_t ab = act1 + (uint32_t)((mrow0 + 16 * mt + lr + lt * 8) * 144)
                            + (uint32_t)(lh * 16);
                #pragma unroll
                for (int ks = 0; ks < 4; ks++)
                    ldsm4(ab + (uint32_t)(ks * 32), a2[ks][mt]);
            }
            #pragma unroll
            for (int nj = 0; nj < 4; nj++) {
                const int cb = nj & 1, nb = cb ^ 1;
                float acc[2][2][4];
                #pragma unroll
                for (int ks = 0; ks < 4; ks++) {
                    #pragma unroll
                    for (int mt = 0; mt < 2; mt++) {
                        if (ks == 0) {
                            mma_fp8_z(acc[mt][0], a2[0][mt], b2[cb][0][0], b2[cb][0][1]);
                            mma_fp8_z(acc[mt][1], a2[0][mt], b2[cb][0][2], b2[cb][0][3]);
                        } else {
                            mma_fp8(acc[mt][0], a2[ks][mt], b2[cb][ks][0], b2[cb][ks][1]);
                            mma_fp8(acc[mt][1], a2[ks][mt], b2[cb][ks][2], b2[cb][ks][3]);
                        }
                    }
                }
                if (nj < 3) {                           // prefetch next B block
                    #pragma unroll
                    for (int ks = 0; ks < 4; ks++)
                        ldsm4(bb2 + (uint32_t)((nj + 1) * 2304 + ks * 32), b2[nb][ks]);
                }
                // epi2: h2_16 = relu(acc/16 + bs1_16) -> act2
                #pragma unroll
                for (int mt = 0; mt < 2; mt++) {
                    int rA = mrow0 + 16 * mt + grp;
                    #pragma unroll
                    for (int sub = 0; sub < 2; sub++) {
                        int c = ncol0 + 16 * nj + 8 * sub + 2 * qd;
                        float2 bv = bs12[c >> 1];
                        float* A = acc[mt][sub];
                        sts_b16(act2 + (uint32_t)(rA * 144 + c),
                                pk2_e4m3(fmaxf(fmaf(A[0], 0.0625f, bv.x), 0.f),
                                         fmaxf(fmaf(A[1], 0.0625f, bv.y), 0.f)));
                        sts_b16(act2 + (uint32_t)((rA + 8) * 144 + c),
                                pk2_e4m3(fmaxf(fmaf(A[2], 0.0625f, bv.x), 0.f),
                                         fmaxf(fmaf(A[3], 0.0625f, bv.y), 0.f)));
                    }
                }
            }
        }

        // ---- preload GEMM3's first B block BEFORE the barrier (ws2 read-only) --
        const uint32_t bb3 = ws2T + (uint32_t)((ncol0 + lr + lh * 8) * 144)
                           + (uint32_t)(lt * 16);
        uint32_t b3[2][4][4];
        #pragma unroll
        for (int ks = 0; ks < 4; ks++)
            ldsm4(bb3 + (uint32_t)(ks * 32), b3[0][ks]);
        PAIRBAR(pid);                                   // pair's h2 rows complete

        // ========= GEMM3 + epi3 fused, B double-buffered =======================
        {
            uint32_t a3[4][2][4];
            #pragma unroll
            for (int mt = 0; mt < 2; mt++) {
                uint32_t ab = act2 + (uint32_t)((mrow0 + 16 * mt + lr + lt * 8) * 144)
                            + (uint32_t)(lh * 16);
                #pragma unroll
                for (int ks = 0; ks < 4; ks++)
                    ldsm4(ab + (uint32_t)(ks * 32), a3[ks][mt]);
            }
            const float2* wfs2 = wfs2a + cur * 64;
            float pA0 = 0.f, pB0 = 0.f, pA1 = 0.f, pB1 = 0.f;
            #pragma unroll
            for (int nj = 0; nj < 4; nj++) {
                const int cb = nj & 1, nb = cb ^ 1;
                float acc[2][2][4];
                #pragma unroll
                for (int ks = 0; ks < 4; ks++) {
                    #pragma unroll
                    for (int mt = 0; mt < 2; mt++) {
                        if (ks == 0) {
                            mma_fp8_z(acc[mt][0], a3[0][mt], b3[cb][0][0], b3[cb][0][1]);
                            mma_fp8_z(acc[mt][1], a3[0][mt], b3[cb][0][2], b3[cb][0][3]);
                        } else {
                            mma_fp8(acc[mt][0], a3[ks][mt], b3[cb][ks][0], b3[cb][ks][1]);
                            mma_fp8(acc[mt][1], a3[ks][mt], b3[cb][ks][2], b3[cb][ks][3]);
                        }
                    }
                }
                if (nj < 3) {
                    #pragma unroll
                    for (int ks = 0; ks < 4; ks++)
                        ldsm4(bb3 + (uint32_t)((nj + 1) * 2304 + ks * 32), b3[nb][ks]);
                }
                // epi3 partial dot for this block
                #pragma unroll
                for (int sub = 0; sub < 2; sub++) {
                    int c = ncol0 + 16 * nj + 8 * sub + 2 * qd;
                    float2 wv = wfs2[c >> 1];
                    float2 bv = bs22[c >> 1];
                    float* A0 = acc[0][sub];
                    float* A1 = acc[1][sub];
                    pA0 = fmaf(wv.x, fmaxf(fmaf(A0[0], 0.00390625f, bv.x), 0.f), pA0);
                    pA0 = fmaf(wv.y, fmaxf(fmaf(A0[1], 0.00390625f, bv.y), 0.f), pA0);
                    pB0 = fmaf(wv.x, fmaxf(fmaf(A0[2], 0.00390625f, bv.x), 0.f), pB0);
                    pB0 = fmaf(wv.y, fmaxf(fmaf(A0[3], 0.00390625f, bv.y), 0.f), pB0);
                    pA1 = fmaf(wv.x, fmaxf(fmaf(A1[0], 0.00390625f, bv.x), 0.f), pA1);
                    pA1 = fmaf(wv.y, fmaxf(fmaf(A1[1], 0.00390625f, bv.y), 0.f), pA1);
                    pB1 = fmaf(wv.x, fmaxf(fmaf(A1[2], 0.00390625f, bv.x), 0.f), pB1);
                    pB1 = fmaf(wv.y, fmaxf(fmaf(A1[3], 0.00390625f, bv.y), 0.f), pB1);
                }
            }
            pA0 += __shfl_xor_sync(0xffffffffu, pA0, 1);
            pA0 += __shfl_xor_sync(0xffffffffu, pA0, 2);
            pB0 += __shfl_xor_sync(0xffffffffu, pB0, 1);
            pB0 += __shfl_xor_sync(0xffffffffu, pB0, 2);
            pA1 += __shfl_xor_sync(0xffffffffu, pA1, 1);
            pA1 += __shfl_xor_sync(0xffffffffu, pA1, 2);
            pB1 += __shfl_xor_sync(0xffffffffu, pB1, 1);
            pB1 += __shfl_xor_sync(0xffffffffu, pB1, 2);
            if (qd == 0 && nhalf == 1) {        // publish col-half-1 partials
                partT[mrow0 + grp]      = pA0;
                partT[mrow0 + grp + 8]  = pB0;
                partT[mrow0 + grp + 16] = pA1;
                partT[mrow0 + grp + 24] = pB1;
            }
            PAIRBAR(pid);
            if (qd == 0 && nhalf == 0) {        // combine + sigmoid + store
                int r0 = mrow0 + grp;
                float t0 = pA0 + partT[r0]      + bfv;
                float t1 = pB0 + partT[r0 + 8]  + bfv;
                float t2 = pA1 + partT[r0 + 16] + bfv;
                float t3 = pB1 + partT[r0 + 24] + bfv;
                float o0 = 1.f / (1.f + __expf(-t0));
                float o1 = 1.f / (1.f + __expf(-t1));
                float o2 = 1.f / (1.f + __expf(-t2));
                float o3 = 1.f / (1.f + __expf(-t3));
                sts_b8(stateT + (uint32_t)((r0)      * 80 + i), (uint32_t)fp8b(o0));
                sts_b8(stateT + (uint32_t)((r0 + 8)  * 80 + i), (uint32_t)fp8b(o1));
                sts_b8(stateT + (uint32_t)((r0 + 16) * 80 + i), (uint32_t)fp8b(o2));
                sts_b8(stateT + (uint32_t)((r0 + 24) * 80 + i), (uint32_t)fp8b(o3));
                out[(size_t)(tb + r0)      * 64 + i] = o0;   // exact f32 output
                out[(size_t)(tb + r0 + 8)  * 64 + i] = o1;
                out[(size_t)(tb + r0 + 16) * 64 + i] = o2;
                out[(size_t)(tb + r0 + 24) * 64 + i] = o3;
            }
        }
        __syncthreads();                        // step boundary: state + bufs sealed
    }
}

extern "C" void kernel_launch(void* const* d_in, const int* in_sizes, int n_in,
                              void* d_out, int out_size) {
    const float* x   = (const float*)d_in[0];
    const float* z   = (const float*)d_in[1];
    const float* Mg  = (const float*)d_in[2];
    const float* Wi  = (const float*)d_in[3];
    const float* bi  = (const float*)d_in[4];
    const float* Ws1 = (const float*)d_in[5];
    const float* bs1 = (const float*)d_in[6];
    const float* Ws2 = (const float*)d_in[7];
    const float* bs2 = (const float*)d_in[8];
    const float* wf  = (const float*)d_in[9];
    const float* bf  = (const float*)d_in[10];
    float* out = (float*)d_out;

    const int B = in_sizes[0] / 64;              // 65536
    const int grid = B / TILE_M;                 // 512

    cudaFuncSetAttribute(gen_causal_kernel,
                         cudaFuncAttributeMaxDynamicSharedMemorySize, SMEM_TOTAL);
    prep_wi_kernel<<<64, 256>>>(Wi, Mg);
    gen_causal_kernel<<<grid, NTH, SMEM_TOTAL>>>(x, z, bi, Ws1, bs1,
                                                 Ws2, bs2, wf, bf, out);
}

// round 15
// speedup vs baseline: 1.0143x; 1.0143x over previous
// Generator_causal on GB300 (compute_103 baseline): warp-level FP8 e4m3 mma.sync +
// ldmatrix. CTA = 256 threads = ONE 128-row batch tile, 8 warps x (16 rows x 128
// cols) -> EVERY intra-step dependency is intra-warp: NO pair barriers, no
// partial-dot exchange; just 2 __syncwarp per step + 1 CTA sync for the shared
// Wi prefetch. Single act buffer (h2 overwrites h1's own rows). Fused
// GEMM+epilogue per 16-col block; padded-stride linear layouts; adjacency mask
// folded into Wi offline; C-zero first-kstep mma. 2 CTAs/SM.
// Scales: state=fp8(v); WiM=fp8(128*Wi*M); Ws=fp8(16*Ws); h=fp8(16*h).
#include <cuda_runtime.h>
#include <cuda_bf16.h>
#include <cstdint>

#define NTH    256
#define TILE_M 128

// device scratch: pre-packed fp8(128*Wi*Mcol) tiles (80B row stride) + z-col wts
__device__ __align__(16) uint8_t g_wi8[64][10240];
__device__ float g_wic16[64][128];

// ---------------- SMEM map (bytes) ----------------
#define OFF_STATE  1024u      // 128 rows x 80B = 10240
#define OFF_ACT    11264u     // h1/h2 shared: 128 x 144B = 18432
#define OFF_WIB    29696u     // 2 bufs x (128 x 80B) = 20480
#define OFF_WS1    50176u     // 128 x 144B = 18432
#define OFF_WS2    68608u     // 18432
#define OFF_VEC    87040u     // wic[2][128]|wfs[2][128]|bis[2][128]|bs1|bs2 = 4096
#define SMEM_TOTAL 91136u

// ---------------- helpers ----------------
__device__ __forceinline__ uint32_t smem_u32(const void* p) {
    uint32_t a;
    asm("{ .reg .u64 t; cvta.to.shared.u64 t, %1; cvt.u32.u64 %0, t; }" : "=r"(a) : "l"(p));
    return a;
}
__device__ __forceinline__ uint16_t pk2_e4m3(float lo, float hi) {
    uint16_t r;
    asm("cvt.rn.satfinite.e4m3x2.f32 %0, %1, %2;" : "=h"(r) : "f"(hi), "f"(lo));
    return r;
}
__device__ __forceinline__ uint32_t pk4_e4m3(float v0, float v1, float v2, float v3) {
    uint16_t lo = pk2_e4m3(v0, v1), hi = pk2_e4m3(v2, v3);
    uint32_t r;
    asm("mov.b32 %0, {%1, %2};" : "=r"(r) : "h"(lo), "h"(hi));
    return r;
}
__device__ __forceinline__ uint8_t fp8b(float v) { return (uint8_t)pk2_e4m3(v, 0.f); }
__device__ __forceinline__ void sts32(uint32_t addr, uint32_t v) {
    asm volatile("st.shared.b32 [%0], %1;" :: "r"(addr), "r"(v) : "memory");
}
__device__ __forceinline__ void sts_b16(uint32_t addr, uint16_t v) {
    asm volatile("st.shared.b16 [%0], %1;" :: "r"(addr), "h"(v) : "memory");
}
__device__ __forceinline__ void sts_b8(uint32_t addr, uint32_t v) {
    asm volatile("st.shared.u8 [%0], %1;" :: "r"(addr), "r"(v) : "memory");
}
__device__ __forceinline__ void sts128(uint32_t addr, uint4 v) {
    asm volatile("st.shared.v4.b32 [%0], {%1,%2,%3,%4};"
                 :: "r"(addr), "r"(v.x), "r"(v.y), "r"(v.z), "r"(v.w) : "memory");
}
__device__ __forceinline__ void ldsm4(uint32_t addr, uint32_t* r) {
    asm volatile("ldmatrix.sync.aligned.m8n8.x4.shared.b16 {%0,%1,%2,%3}, [%4];"
                 : "=r"(r[0]), "=r"(r[1]), "=r"(r[2]), "=r"(r[3]) : "r"(addr));
}
__device__ __forceinline__ void mma_fp8(float* c, const uint32_t* a, uint32_t b0, uint32_t b1) {
    asm volatile("mma.sync.aligned.m16n8k32.row.col.f32.e4m3.e4m3.f32 "
                 "{%0,%1,%2,%3}, {%4,%5,%6,%7}, {%8,%9}, {%0,%1,%2,%3};"
                 : "+f"(c[0]), "+f"(c[1]), "+f"(c[2]), "+f"(c[3])
                 : "r"(a[0]), "r"(a[1]), "r"(a[2]), "r"(a[3]), "r"(b0), "r"(b1));
}
__device__ __forceinline__ void mma_fp8_z(float* d, const uint32_t* a, uint32_t b0, uint32_t b1) {
    asm volatile("mma.sync.aligned.m16n8k32.row.col.f32.e4m3.e4m3.f32 "
                 "{%0,%1,%2,%3}, {%4,%5,%6,%7}, {%8,%9}, {%10,%11,%12,%13};"
                 : "=f"(d[0]), "=f"(d[1]), "=f"(d[2]), "=f"(d[3])
                 : "r"(a[0]), "r"(a[1]), "r"(a[2]), "r"(a[3]), "r"(b0), "r"(b1),
                   "f"(0.f), "f"(0.f), "f"(0.f), "f"(0.f));
}

// prologue: fold adjacency column into Wi -> fp8(128 * Wi * M[k][s]), 80B rows
__global__ void prep_wi_kernel(const float* __restrict__ Wi, const float* __restrict__ Mg) {
    const int s = blockIdx.x;
    const float* src = Wi + (size_t)s * 8320;
    for (int idx = threadIdx.x; idx < 8320; idx += 256) {
        int n = idx / 65, k = idx - n * 65;
        float v = __ldg(src + idx);
        if (k < 64) g_wi8[s][n * 80 + k] = fp8b(128.f * v * __ldg(Mg + k * 64 + s));
        else        g_wic16[s][n] = 16.f * v;
    }
}

__global__ void __launch_bounds__(NTH, 2)
gen_causal_kernel(const float* __restrict__ x,   const float* __restrict__ z,
                  const float* __restrict__ bi,  const float* __restrict__ Ws1,
                  const float* __restrict__ bs1, const float* __restrict__ Ws2,
                  const float* __restrict__ bs2, const float* __restrict__ wf,
                  const float* __restrict__ bf,  float* __restrict__ out)
{
    extern __shared__ char smem[];
    const int tid  = threadIdx.x;
    const int lane = tid & 31;
    const int w    = tid >> 5;
    const int mrow0 = w << 4;                   // warp's 16 rows
    const int grp   = lane >> 2, qd = lane & 3;
    const int lr = lane & 7, lt = (lane >> 3) & 1, lh = lane >> 4;
    const int tb    = blockIdx.x * TILE_M;
    const uint32_t sb     = smem_u32(smem);
    const uint32_t stateT = sb + OFF_STATE;     // 80B rows
    const uint32_t actT   = sb + OFF_ACT;       // 144B rows (h1 then h2, same rows)
    const uint32_t ws1T   = sb + OFF_WS1;
    const uint32_t ws2T   = sb + OFF_WS2;

    float* wicV = reinterpret_cast<float*>(smem + OFF_VEC);   // [2][128]
    float* wfsV = wicV + 256;                                 // [2][128]
    float* bisV = wfsV + 256;                                 // [2][128] (16*bi)
    float* bs1s = bisV + 256;                                 // [128] (16*bs1)
    float* bs2s = bs1s + 128;                                 // [128]
    const float2* wic2a = reinterpret_cast<const float2*>(wicV);
    const float2* wfs2a = reinterpret_cast<const float2*>(wfsV);
    const float2* bis2a = reinterpret_cast<const float2*>(bisV);
    const float2* bs12  = reinterpret_cast<const float2*>(bs1s);
    const float2* bs22  = reinterpret_cast<const float2*>(bs2s);

    // ---- one-time init ----
    #pragma unroll 4
    for (int it = 0; it < 16; it++) {           // Ws1/Ws2 -> fp8(16*w), 144B rows
        int q = it * NTH + tid;
        int n = q >> 5, k4 = (q & 31) * 4;
        float4 a = __ldg(reinterpret_cast<const float4*>(Ws1) + q);
        float4 b = __ldg(reinterpret_cast<const float4*>(Ws2) + q);
        uint32_t o = (uint32_t)(n * 144 + k4);
        sts32(ws1T + o, pk4_e4m3(16.f * a.x, 16.f * a.y, 16.f * a.z, 16.f * a.w));
        sts32(ws2T + o, pk4_e4m3(16.f * b.x, 16.f * b.y, 16.f * b.z, 16.f * b.w));
    }
    #pragma unroll 4
    for (int it = 0; it < 8; it++) {            // state <- fp8(x), 80B rows
        int q = it * NTH + tid;
        int r = q >> 4, c4 = (q & 15) << 2;
        float4 v = __ldg(reinterpret_cast<const float4*>(x) + (size_t)blockIdx.x * 2048 + q);
        sts32(stateT + (uint32_t)(r * 80 + c4), pk4_e4m3(v.x, v.y, v.z, v.w));
    }
    #pragma unroll
    for (int it = 0; it < 3; it++) {            // Wi buffer 0 (640 uint4)
        int q = it * NTH + tid;
        if (q < 640) {
            int o = q * 16;
            sts128(sb + OFF_WIB + o, *reinterpret_cast<const uint4*>(g_wi8[0] + o));
        }
    }
    if (tid < 128) {
        wicV[tid] = g_wic16[0][tid];
        wfsV[tid] = __ldg(wf + tid);
        bisV[tid] = 16.f * __ldg(bi + tid);
        bs1s[tid] = 16.f * __ldg(bs1 + tid);
        bs2s[tid] = __ldg(bs2 + tid);
    }
    __syncthreads();

    const int rA = mrow0 + grp;                 // thread's two output rows
    const float* zA_p = z + (size_t)(tb + rA) * 64;
    const float* zB_p = z + (size_t)(tb + rA + 8) * 64;

    #pragma unroll 1
    for (int i = 0; i < 64; i++) {
        const int cur = i & 1, nxt = cur ^ 1;
        const float bfv = __ldg(bf + i);
        const float zA = __ldg(zA_p + i);
        const float zB = __ldg(zB_p + i);

        // ========= GEMM1 + epi1 fused (K=64; A=state rows mrow0..+15) ==========
        {
            const uint32_t wib = sb + OFF_WIB + (uint32_t)cur * 10240u;
            uint32_t a1[2][4];
            uint32_t ab = stateT + (uint32_t)((mrow0 + lr + lt * 8) * 80)
                        + (uint32_t)(lh * 16);
            ldsm4(ab,       a1[0]);
            ldsm4(ab + 32u, a1[1]);
            const uint32_t bb = wib + (uint32_t)((lr + lh * 8) * 80)
                              + (uint32_t)(lt * 16);    // +1280 per 16-col block
            const float2* wic2 = wic2a + cur * 64;
            const float2* bis2 = bis2a + cur * 64;
            #pragma unroll
            for (int cblk = 0; cblk < 8; cblk++) {
                uint32_t b0[4], b1[4];
                ldsm4(bb + (uint32_t)(cblk * 1280),       b0);
                ldsm4(bb + (uint32_t)(cblk * 1280) + 32u, b1);
                float acc[2][4];
                mma_fp8_z(acc[0], a1[0], b0[0], b0[1]);
                mma_fp8_z(acc[1], a1[0], b0[2], b0[3]);
                mma_fp8(acc[0], a1[1], b1[0], b1[1]);
                mma_fp8(acc[1], a1[1], b1[2], b1[3]);
                // epi1: h1_16 = relu(acc/8 + wic16*z + bi16) -> own act rows
                #pragma unroll
                for (int sub = 0; sub < 2; sub++) {
                    int c = cblk * 16 + 8 * sub + 2 * qd;
                    float2 wv = wic2[c >> 1];
                    float2 bv = bis2[c >> 1];
                    float* A = acc[sub];
                    float v0 = fmaxf(fmaf(A[0], 0.125f, fmaf(wv.x, zA, bv.x)), 0.f);
                    float v1 = fmaxf(fmaf(A[1], 0.125f, fmaf(wv.y, zA, bv.y)), 0.f);
                    float v2 = fmaxf(fmaf(A[2], 0.125f, fmaf(wv.x, zB, bv.x)), 0.f);
                    float v3 = fmaxf(fmaf(A[3], 0.125f, fmaf(wv.y, zB, bv.y)), 0.f);
                    sts_b16(actT + (uint32_t)(rA * 144 + c), pk2_e4m3(v0, v1));
                    sts_b16(actT + (uint32_t)((rA + 8) * 144 + c), pk2_e4m3(v2, v3));
                }
            }
        }

        // ---- cooperative prefetch of step i+1's Wi (sealed by boundary sync) --
        if (i < 63) {
            const uint8_t* srcw = g_wi8[i + 1];
            const uint32_t dst = sb + OFF_WIB + (uint32_t)nxt * 10240u;
            #pragma unroll
            for (int it = 0; it < 3; it++) {
                int q = it * NTH + tid;
                if (q < 640) {
                    int o = q * 16;
                    sts128(dst + o, *reinterpret_cast<const uint4*>(srcw + o));
                }
            }
            if (tid < 128) {
                wicV[nxt * 128 + tid] = g_wic16[i + 1][tid];
                wfsV[nxt * 128 + tid] = __ldg(wf + (i + 1) * 128 + tid);
            } else {
                bisV[nxt * 128 + tid - 128] = 16.f * __ldg(bi + (i + 1) * 128 + tid - 128);
            }
        }
        __syncwarp();                           // own h1 rows visible warp-wide

        // ========= GEMM2 + epi2 fused (K=128; A=own act rows; h2 -> same rows) =
        {
            uint32_t a2[4][4];                  // [ks] -- preloaded before stores
            uint32_t ab = actT + (uint32_t)((mrow0 + lr + lt * 8) * 144)
                        + (uint32_t)(lh * 16);
            #pragma unroll
            for (int ks = 0; ks < 4; ks++)
                ldsm4(ab + (uint32_t)(ks * 32), a2[ks]);
            const uint32_t bb = ws1T + (uint32_t)((lr + lh * 8) * 144)
                              + (uint32_t)(lt * 16);    // +2304 per 16-col block
            #pragma unroll
            for (int cblk = 0; cblk < 8; cblk++) {
                float acc[2][4];
                #pragma unroll
                for (int ks = 0; ks < 4; ks++) {
                    uint32_t b[4];
                    ldsm4(bb + (uint32_t)(cblk * 2304 + ks * 32), b);
                    if (ks == 0) {
                        mma_fp8_z(acc[0], a2[0], b[0], b[1]);
                        mma_fp8_z(acc[1], a2[0], b[2], b[3]);
                    } else {
                        mma_fp8(acc[0], a2[ks], b[0], b[1]);
                        mma_fp8(acc[1], a2[ks], b[2], b[3]);
                    }
                }
                // epi2: h2_16 = relu(acc/16 + bs1_16) -> same act rows
                #pragma unroll
                for (int sub = 0; sub < 2; sub++) {
                    int c = cblk * 16 + 8 * sub + 2 * qd;
                    float2 bv = bs12[c >> 1];
                    float* A = acc[sub];
                    sts_b16(actT + (uint32_t)(rA * 144 + c),
                            pk2_e4m3(fmaxf(fmaf(A[0], 0.0625f, bv.x), 0.f),
                                     fmaxf(fmaf(A[1], 0.0625f, bv.y), 0.f)));
                    sts_b16(actT + (uint32_t)((rA + 8) * 144 + c),
                            pk2_e4m3(fmaxf(fmaf(A[2], 0.0625f, bv.x), 0.f),
                                     fmaxf(fmaf(A[3], 0.0625f, bv.y), 0.f)));
                }
            }
        }
        __syncwarp();                           // own h2 rows visible warp-wide

        // ========= GEMM3 + epi3 fused (full 128-col dot in-warp) ===============
        {
            uint32_t a3[4][4];
            uint32_t ab = actT + (uint32_t)((mrow0 + lr + lt * 8) * 144)
                        + (uint32_t)(lh * 16);
            #pragma unroll
            for (int ks = 0; ks < 4; ks++)
                ldsm4(ab + (uint32_t)(ks * 32), a3[ks]);
            const uint32_t bb = ws2T + (uint32_t)((lr + lh * 8) * 144)
                              + (uint32_t)(lt * 16);
            const float2* wfs2 = wfs2a + cur * 64;
            float pA = 0.f, pB = 0.f;
            #pragma unroll
            for (int cblk = 0; cblk < 8; cblk++) {
                float acc[2][4];
                #pragma unroll
                for (int ks = 0; ks < 4; ks++) {
                    uint32_t b[4];
                    ldsm4(bb + (uint32_t)(cblk * 2304 + ks * 32), b);
                    if (ks == 0) {
                        mma_fp8_z(acc[0], a3[0], b[0], b[1]);
                        mma_fp8_z(acc[1], a3[0], b[2], b[3]);
                    } else {
                        mma_fp8(acc[0], a3[ks], b[0], b[1]);
                        mma_fp8(acc[1], a3[ks], b[2], b[3]);
                    }
                }
                #pragma unroll
                for (int sub = 0; sub < 2; sub++) {
                    int c = cblk * 16 + 8 * sub + 2 * qd;
                    float2 wv = wfs2[c >> 1];
                    float2 bv = bs22[c >> 1];
                    float* A = acc[sub];
                    pA = fmaf(wv.x, fmaxf(fmaf(A[0], 0.00390625f, bv.x), 0.f), pA);
                    pA = fmaf(wv.y, fmaxf(fmaf(A[1], 0.00390625f, bv.y), 0.f), pA);
                    pB = fmaf(wv.x, fmaxf(fmaf(A[2], 0.00390625f, bv.x), 0.f), pB);
                    pB = fmaf(wv.y, fmaxf(fmaf(A[3], 0.00390625f, bv.y), 0.f), pB);
                }
            }
            // reduce across the 4 lanes of the quad (cols) -- in-warp only
            pA += __shfl_xor_sync(0xffffffffu, pA, 1);
            pA += __shfl_xor_sync(0xffffffffu, pA, 2);
            pB += __shfl_xor_sync(0xffffffffu, pB, 1);
            pB += __shfl_xor_sync(0xffffffffu, pB, 2);
            if (qd == 0) {                      // 8 lanes/warp: 2 rows each
                float o0 = 1.f / (1.f + __expf(-(pA + bfv)));
                float o1 = 1.f / (1.f + __expf(-(pB + bfv)));
                sts_b8(stateT + (uint32_t)(rA * 80 + i),       (uint32_t)fp8b(o0));
                sts_b8(stateT + (uint32_t)((rA + 8) * 80 + i), (uint32_t)fp8b(o1));
                out[(size_t)(tb + rA) * 64 + i]     = o0;   // exact f32 output
                out[(size_t)(tb + rA + 8) * 64 + i] = o1;
            }
        }
        __syncthreads();                        // step boundary: Wi/vec bufs sealed
    }
}

extern "C" void kernel_launch(void* const* d_in, const int* in_sizes, int n_in,
                              void* d_out, int out_size) {
    const float* x   = (const float*)d_in[0];
    const float* z   = (const float*)d_in[1];
    const float* Mg  = (const float*)d_in[2];
    const float* Wi  = (const float*)d_in[3];
    const float* bi  = (const float*)d_in[4];
    const float* Ws1 = (const float*)d_in[5];
    const float* bs1 = (const float*)d_in[6];
    const float* Ws2 = (const float*)d_in[7];
    const float* bs2 = (const float*)d_in[8];
    const float* wf  = (const float*)d_in[9];
    const float* bf  = (const float*)d_in[10];
    float* out = (float*)d_out;

    const int B = in_sizes[0] / 64;              // 65536
    const int grid = B / TILE_M;                 // 512

    cudaFuncSetAttribute(gen_causal_kernel,
                         cudaFuncAttributeMaxDynamicSharedMemorySize, SMEM_TOTAL);
    prep_wi_kernel<<<64, 256>>>(Wi, Mg);
    gen_causal_kernel<<<grid, NTH, SMEM_TOTAL>>>(x, z, bi, Ws1, bs1,
                                                 Ws2, bs2, wf, bf, out);
}

// round 16
// speedup vs baseline: 1.0351x; 1.0206x over previous
// Generator_causal on GB300 (compute_103 baseline): warp-level FP8 e4m3 mma.sync +
// ldmatrix. CTA = 256 threads = ONE 128-row batch tile (8 warps = 4 warp pairs).
// R16 = R13 (best) + (1) Wi-prefetch LDGs issued at step top, STS after GEMM1
// (hides L2 latency under mma stream), (2) step loop unrolled x2 so cur/nxt are
// compile-time. Fused GEMM+epilogue per 16-col block; padded-stride linear
// layouts; adjacency mask folded into Wi offline; C-zero first-kstep mma;
// pair-local barriers; one CTA sync per step. 2 CTAs/SM.
// Scales: state=fp8(v); WiM=fp8(128*Wi*M); Ws=fp8(16*Ws); h=fp8(16*h).
#include <cuda_runtime.h>
#include <cuda_bf16.h>
#include <cstdint>

#define NTH    256
#define TILE_M 128

__device__ __align__(16) uint8_t g_wi8[64][10240];
__device__ float g_wic16[64][128];

#define OFF_STATE  1024u      // 128 rows x 80B = 10240
#define OFF_ACT1   11264u     // h1: 128 x 144B = 18432
#define OFF_ACT2   29696u     // h2: 128 x 144B = 18432
#define OFF_WIB    48128u     // 2 bufs x (128 x 80B) = 20480
#define OFF_WS1    68608u     // 128 x 144B = 18432
#define OFF_WS2    87040u     // 18432
#define OFF_VEC    105472u    // wic[2][128]|wfs[2][128]|bis[2][128]|bs1|bs2|part
#define SMEM_TOTAL 110080u

__device__ __forceinline__ uint32_t smem_u32(const void* p) {
    uint32_t a;
    asm("{ .reg .u64 t; cvta.to.shared.u64 t, %1; cvt.u32.u64 %0, t; }" : "=r"(a) : "l"(p));
    return a;
}
__device__ __forceinline__ uint16_t pk2_e4m3(float lo, float hi) {
    uint16_t r;
    asm("cvt.rn.satfinite.e4m3x2.f32 %0, %1, %2;" : "=h"(r) : "f"(hi), "f"(lo));
    return r;
}
__device__ __forceinline__ uint32_t pk4_e4m3(float v0, float v1, float v2, float v3) {
    uint16_t lo = pk2_e4m3(v0, v1), hi = pk2_e4m3(v2, v3);
    uint32_t r;
    asm("mov.b32 %0, {%1, %2};" : "=r"(r) : "h"(lo), "h"(hi));
    return r;
}
__device__ __forceinline__ uint8_t fp8b(float v) { return (uint8_t)pk2_e4m3(v, 0.f); }
__device__ __forceinline__ void sts32(uint32_t addr, uint32_t v) {
    asm volatile("st.shared.b32 [%0], %1;" :: "r"(addr), "r"(v) : "memory");
}
__device__ __forceinline__ void sts_b16(uint32_t addr, uint16_t v) {
    asm volatile("st.shared.b16 [%0], %1;" :: "r"(addr), "h"(v) : "memory");
}
__device__ __forceinline__ void sts_b8(uint32_t addr, uint32_t v) {
    asm volatile("st.shared.u8 [%0], %1;" :: "r"(addr), "r"(v) : "memory");
}
__device__ __forceinline__ void sts128(uint32_t addr, uint4 v) {
    asm volatile("st.shared.v4.b32 [%0], {%1,%2,%3,%4};"
                 :: "r"(addr), "r"(v.x), "r"(v.y), "r"(v.z), "r"(v.w) : "memory");
}
__device__ __forceinline__ void ldsm4(uint32_t addr, uint32_t* r) {
    asm volatile("ldmatrix.sync.aligned.m8n8.x4.shared.b16 {%0,%1,%2,%3}, [%4];"
                 : "=r"(r[0]), "=r"(r[1]), "=r"(r[2]), "=r"(r[3]) : "r"(addr));
}
__device__ __forceinline__ void mma_fp8(float* c, const uint32_t* a, uint32_t b0, uint32_t b1) {
    asm volatile("mma.sync.aligned.m16n8k32.row.col.f32.e4m3.e4m3.f32 "
                 "{%0,%1,%2,%3}, {%4,%5,%6,%7}, {%8,%9}, {%0,%1,%2,%3};"
                 : "+f"(c[0]), "+f"(c[1]), "+f"(c[2]), "+f"(c[3])
                 : "r"(a[0]), "r"(a[1]), "r"(a[2]), "r"(a[3]), "r"(b0), "r"(b1));
}
__device__ __forceinline__ void mma_fp8_z(float* d, const uint32_t* a, uint32_t b0, uint32_t b1) {
    asm volatile("mma.sync.aligned.m16n8k32.row.col.f32.e4m3.e4m3.f32 "
                 "{%0,%1,%2,%3}, {%4,%5,%6,%7}, {%8,%9}, {%10,%11,%12,%13};"
                 : "=f"(d[0]), "=f"(d[1]), "=f"(d[2]), "=f"(d[3])
                 : "r"(a[0]), "r"(a[1]), "r"(a[2]), "r"(a[3]), "r"(b0), "r"(b1),
                   "f"(0.f), "f"(0.f), "f"(0.f), "f"(0.f));
}
#define PAIRBAR(id) asm volatile("bar.sync %0, 64;" :: "r"(id) : "memory")

// prologue: fold adjacency column into Wi -> fp8(128 * Wi * M[k][s]), 80B rows
__global__ void prep_wi_kernel(const float* __restrict__ Wi, const float* __restrict__ Mg) {
    const int s = blockIdx.x;
    const float* src = Wi + (size_t)s * 8320;
    for (int idx = threadIdx.x; idx < 8320; idx += 256) {
        int n = idx / 65, k = idx - n * 65;
        float v = __ldg(src + idx);
        if (k < 64) g_wi8[s][n * 80 + k] = fp8b(128.f * v * __ldg(Mg + k * 64 + s));
        else        g_wic16[s][n] = 16.f * v;
    }
}

__global__ void __launch_bounds__(NTH, 2)
gen_causal_kernel(const float* __restrict__ x,   const float* __restrict__ z,
                  const float* __restrict__ bi,  const float* __restrict__ Ws1,
                  const float* __restrict__ bs1, const float* __restrict__ Ws2,
                  const float* __restrict__ bs2, const float* __restrict__ wf,
                  const float* __restrict__ bf,  float* __restrict__ out)
{
    extern __shared__ char smem[];
    const int tid  = threadIdx.x;
    const int lane = tid & 31;
    const int w    = tid >> 5;
    const int pair = w >> 1;
    const int mrow0 = pair << 5;
    const int nhalf = w & 1;
    const int ncol0 = nhalf << 6;
    const int pid   = 1 + pair;
    const int grp   = lane >> 2, qd = lane & 3;
    const int lr = lane & 7, lt = (lane >> 3) & 1, lh = lane >> 4;
    const int tb    = blockIdx.x * TILE_M;
    const uint32_t sb     = smem_u32(smem);
    const uint32_t stateT = sb + OFF_STATE;
    const uint32_t act1   = sb + OFF_ACT1;
    const uint32_t act2   = sb + OFF_ACT2;
    const uint32_t ws1T   = sb + OFF_WS1;
    const uint32_t ws2T   = sb + OFF_WS2;

    float* wicV = reinterpret_cast<float*>(smem + OFF_VEC);
    float* wfsV = wicV + 256;
    float* bisV = wfsV + 256;
    float* bs1s = bisV + 256;
    float* bs2s = bs1s + 128;
    float* partT = bs2s + 128;
    const float2* wic2a = reinterpret_cast<const float2*>(wicV);
    const float2* wfs2a = reinterpret_cast<const float2*>(wfsV);
    const float2* bis2a = reinterpret_cast<const float2*>(bisV);
    const float2* bs12  = reinterpret_cast<const float2*>(bs1s);
    const float2* bs22  = reinterpret_cast<const float2*>(bs2s);

    // ---- one-time init ----
    #pragma unroll 4
    for (int it = 0; it < 16; it++) {
        int q = it * NTH + tid;
        int n = q >> 5, k4 = (q & 31) * 4;
        float4 a = __ldg(reinterpret_cast<const float4*>(Ws1) + q);
        float4 b = __ldg(reinterpret_cast<const float4*>(Ws2) + q);
        uint32_t o = (uint32_t)(n * 144 + k4);
        sts32(ws1T + o, pk4_e4m3(16.f * a.x, 16.f * a.y, 16.f * a.z, 16.f * a.w));
        sts32(ws2T + o, pk4_e4m3(16.f * b.x, 16.f * b.y, 16.f * b.z, 16.f * b.w));
    }
    #pragma unroll 4
    for (int it = 0; it < 8; it++) {
        int q = it * NTH + tid;
        int r = q >> 4, c4 = (q & 15) << 2;
        float4 v = __ldg(reinterpret_cast<const float4*>(x) + (size_t)blockIdx.x * 2048 + q);
        sts32(stateT + (uint32_t)(r * 80 + c4), pk4_e4m3(v.x, v.y, v.z, v.w));
    }
    #pragma unroll
    for (int it = 0; it < 3; it++) {
        int q = it * NTH + tid;
        if (q < 640) {
            int o = q * 16;
            sts128(sb + OFF_WIB + o, *reinterpret_cast<const uint4*>(g_wi8[0] + o));
        }
    }
    if (tid < 128) {
        wicV[tid] = g_wic16[0][tid];
        wfsV[tid] = __ldg(wf + tid);
        bisV[tid] = 16.f * __ldg(bi + tid);
        bs1s[tid] = 16.f * __ldg(bs1 + tid);
        bs2s[tid] = __ldg(bs2 + tid);
    }
    __syncthreads();

    const float* zbase = z + (size_t)(tb + mrow0 + grp) * 64;

    #pragma unroll 2
    for (int i = 0; i < 64; i++) {
        const int cur = i & 1, nxt = cur ^ 1;
        const float bfv = __ldg(bf + i);
        float zr[4];
        #pragma unroll
        for (int kq = 0; kq < 4; kq++)
            zr[kq] = __ldg(zbase + kq * 512 + i);

        // ---- Wi prefetch LDGs at step top (STS deferred past GEMM1) ----
        uint4 pw0 = {}, pw1 = {}, pw2 = {};
        float pv0 = 0.f, pv1 = 0.f;
        const bool pf = (i < 63);
        if (pf) {
            const uint8_t* srcw = g_wi8[i + 1];
            pw0 = *reinterpret_cast<const uint4*>(srcw + (size_t)tid * 16);
            pw1 = *reinterpret_cast<const uint4*>(srcw + (size_t)(tid + 256) * 16);
            if (tid < 128) {
                pw2 = *reinterpret_cast<const uint4*>(srcw + (size_t)(tid + 512) * 16);
                pv0 = g_wic16[i + 1][tid];
                pv1 = __ldg(wf + (i + 1) * 128 + tid);
            } else {
                pv0 = 16.f * __ldg(bi + (i + 1) * 128 + tid - 128);
            }
        }

        // ========= GEMM1 + epi1 fused (K=64, strides 80/80) ====================
        {
            const uint32_t wib = sb + OFF_WIB + (uint32_t)cur * 10240u;
            uint32_t a1[2][2][4];                       // [ks][mt]
            #pragma unroll
            for (int mt = 0; mt < 2; mt++) {
                uint32_t ab = stateT + (uint32_t)((mrow0 + 16 * mt + lr + lt * 8) * 80)
                            + (uint32_t)(lh * 16);
                ldsm4(ab,       a1[0][mt]);
                ldsm4(ab + 32u, a1[1][mt]);
            }
            const float2* wic2 = wic2a + cur * 64;
            const float2* bis2 = bis2a + cur * 64;
            #pragma unroll
            for (int nj = 0; nj < 4; nj++) {
                float acc[2][2][4];                     // [mt][sub]
                uint32_t bb = wib + (uint32_t)((ncol0 + 16 * nj + lr + lh * 8) * 80)
                            + (uint32_t)(lt * 16);
                uint32_t b0[4], b1[4];
                ldsm4(bb,       b0);
                ldsm4(bb + 32u, b1);
                #pragma unroll
                for (int mt = 0; mt < 2; mt++) {
                    mma_fp8_z(acc[mt][0], a1[0][mt], b0[0], b0[1]);
                    mma_fp8_z(acc[mt][1], a1[0][mt], b0[2], b0[3]);
                    mma_fp8(acc[mt][0], a1[1][mt], b1[0], b1[1]);
                    mma_fp8(acc[mt][1], a1[1][mt], b1[2], b1[3]);
                }
                #pragma unroll
                for (int mt = 0; mt < 2; mt++) {
                    int rA = mrow0 + 16 * mt + grp;
                    float zA = zr[2 * mt], zB = zr[2 * mt + 1];
                    #pragma unroll
                    for (int sub = 0; sub < 2; sub++) {
                        int c = ncol0 + 16 * nj + 8 * sub + 2 * qd;
                        float2 wv = wic2[c >> 1];
                        float2 bv = bis2[c >> 1];
                        float* A = acc[mt][sub];
                        float v0 = fmaxf(fmaf(A[0], 0.125f, fmaf(wv.x, zA, bv.x)), 0.f);
                        float v1 = fmaxf(fmaf(A[1], 0.125f, fmaf(wv.y, zA, bv.y)), 0.f);
                        float v2 = fmaxf(fmaf(A[2], 0.125f, fmaf(wv.x, zB, bv.x)), 0.f);
                        float v3 = fmaxf(fmaf(A[3], 0.125f, fmaf(wv.y, zB, bv.y)), 0.f);
                        sts_b16(act1 + (uint32_t)(rA * 144 + c), pk2_e4m3(v0, v1));
                        sts_b16(act1 + (uint32_t)((rA + 8) * 144 + c), pk2_e4m3(v2, v3));
                    }
                }
            }
        }

        // ---- commit prefetched Wi/vectors (buffers sealed by boundary sync) ----
        if (pf) {
            const uint32_t dst = sb + OFF_WIB + (uint32_t)nxt * 10240u;
            sts128(dst + (uint32_t)tid * 16u, pw0);
            sts128(dst + (uint32_t)(tid + 256) * 16u, pw1);
            if (tid < 128) {
                sts128(dst + (uint32_t)(tid + 512) * 16u, pw2);
                wicV[nxt * 128 + tid] = pv0;
                wfsV[nxt * 128 + tid] = pv1;
            } else {
                bisV[nxt * 128 + tid - 128] = pv0;
            }
        }
        PAIRBAR(pid);                           // pair's h1 rows complete

        // ========= GEMM2 + epi2 fused (K=128, strides 144/144) =================
        {
            uint32_t a2[4][2][4];                       // [ks][mt]
            #pragma unroll
            for (int mt = 0; mt < 2; mt++) {
                uint32_t ab = act1 + (uint32_t)((mrow0 + 16 * mt + lr + lt * 8) * 144)
                            + (uint32_t)(lh * 16);
                #pragma unroll
                for (int ks = 0; ks < 4; ks++)
                    ldsm4(ab + (uint32_t)(ks * 32), a2[ks][mt]);
            }
            #pragma unroll
            for (int nj = 0; nj < 4; nj++) {
                float acc[2][2][4];
                uint32_t bb = ws1T + (uint32_t)((ncol0 + 16 * nj + lr + lh * 8) * 144)
                            + (uint32_t)(lt * 16);
                #pragma unroll
                for (int ks = 0; ks < 4; ks++) {
                    uint32_t b[4];
                    ldsm4(bb + (uint32_t)(ks * 32), b);
                    #pragma unroll
                    for (int mt = 0; mt < 2; mt++) {
                        if (ks == 0) {
                            mma_fp8_z(acc[mt][0], a2[0][mt], b[0], b[1]);
                            mma_fp8_z(acc[mt][1], a2[0][mt], b[2], b[3]);
                        } else {
                            mma_fp8(acc[mt][0], a2[ks][mt], b[0], b[1]);
                            mma_fp8(acc[mt][1], a2[ks][mt], b[2], b[3]);
                        }
                    }
                }
                #pragma unroll
                for (int mt = 0; mt < 2; mt++) {
                    int rA = mrow0 + 16 * mt + grp;
                    #pragma unroll
                    for (int sub = 0; sub < 2; sub++) {
                        int c = ncol0 + 16 * nj + 8 * sub + 2 * qd;
                        float2 bv = bs12[c >> 1];
                        float* A = acc[mt][sub];
                        sts_b16(act2 + (uint32_t)(rA * 144 + c),
                                pk2_e4m3(fmaxf(fmaf(A[0], 0.0625f, bv.x), 0.f),
                                         fmaxf(fmaf(A[1], 0.0625f, bv.y), 0.f)));
                        sts_b16(act2 + (uint32_t)((rA + 8) * 144 + c),
                                pk2_e4m3(fmaxf(fmaf(A[2], 0.0625f, bv.x), 0.f),
                                         fmaxf(fmaf(A[3], 0.0625f, bv.y), 0.f)));
                    }
                }
            }
        }
        PAIRBAR(pid);                           // pair's h2 rows complete

        // ========= GEMM3 + epi3 fused ==========================================
        {
            uint32_t a3[4][2][4];
            #pragma unroll
            for (int mt = 0; mt < 2; mt++) {
                uint32_t ab = act2 + (uint32_t)((mrow0 + 16 * mt + lr + lt * 8) * 144)
                            + (uint32_t)(lh * 16);
                #pragma unroll
                for (int ks = 0; ks < 4; ks++)
                    ldsm4(ab + (uint32_t)(ks * 32), a3[ks][mt]);
            }
            const float2* wfs2 = wfs2a + cur * 64;
            float pA0 = 0.f, pB0 = 0.f, pA1 = 0.f, pB1 = 0.f;
            #pragma unroll
            for (int nj = 0; nj < 4; nj++) {
                float acc[2][2][4];
                uint32_t bb = ws2T + (uint32_t)((ncol0 + 16 * nj + lr + lh * 8) * 144)
                            + (uint32_t)(lt * 16);
                #pragma unroll
                for (int ks = 0; ks < 4; ks++) {
                    uint32_t b[4];
                    ldsm4(bb + (uint32_t)(ks * 32), b);
                    #pragma unroll
                    for (int mt = 0; mt < 2; mt++) {
                        if (ks == 0) {
                            mma_fp8_z(acc[mt][0], a3[0][mt], b[0], b[1]);
                            mma_fp8_z(acc[mt][1], a3[0][mt], b[2], b[3]);
                        } else {
                            mma_fp8(acc[mt][0], a3[ks][mt], b[0], b[1]);
                            mma_fp8(acc[mt][1], a3[ks][mt], b[2], b[3]);
                        }
                    }
                }
                #pragma unroll
                for (int sub = 0; sub < 2; sub++) {
                    int c = ncol0 + 16 * nj + 8 * sub + 2 * qd;
                    float2 wv = wfs2[c >> 1];
                    float2 bv = bs22[c >> 1];
                    float* A0 = acc[0][sub];
                    float* A1 = acc[1][sub];
                    pA0 = fmaf(wv.x, fmaxf(fmaf(A0[0], 0.00390625f, bv.x), 0.f), pA0);
                    pA0 = fmaf(wv.y, fmaxf(fmaf(A0[1], 0.00390625f, bv.y), 0.f), pA0);
                    pB0 = fmaf(wv.x, fmaxf(fmaf(A0[2], 0.00390625f, bv.x), 0.f), pB0);
                    pB0 = fmaf(wv.y, fmaxf(fmaf(A0[3], 0.00390625f, bv.y), 0.f), pB0);
                    pA1 = fmaf(wv.x, fmaxf(fmaf(A1[0], 0.00390625f, bv.x), 0.f), pA1);
                    pA1 = fmaf(wv.y, fmaxf(fmaf(A1[1], 0.00390625f, bv.y), 0.f), pA1);
                    pB1 = fmaf(wv.x, fmaxf(fmaf(A1[2], 0.00390625f, bv.x), 0.f), pB1);
                    pB1 = fmaf(wv.y, fmaxf(fmaf(A1[3], 0.00390625f, bv.y), 0.f), pB1);
                }
            }
            pA0 += __shfl_xor_sync(0xffffffffu, pA0, 1);
            pA0 += __shfl_xor_sync(0xffffffffu, pA0, 2);
            pB0 += __shfl_xor_sync(0xffffffffu, pB0, 1);
            pB0 += __shfl_xor_sync(0xffffffffu, pB0, 2);
            pA1 += __shfl_xor_sync(0xffffffffu, pA1, 1);
            pA1 += __shfl_xor_sync(0xffffffffu, pA1, 2);
            pB1 += __shfl_xor_sync(0xffffffffu, pB1, 1);
            pB1 += __shfl_xor_sync(0xffffffffu, pB1, 2);
            if (qd == 0 && nhalf == 1) {
                partT[mrow0 + grp]      = pA0;
                partT[mrow0 + grp + 8]  = pB0;
                partT[mrow0 + grp + 16] = pA1;
                partT[mrow0 + grp + 24] = pB1;
            }
            PAIRBAR(pid);
            if (qd == 0 && nhalf == 0) {
                int r0 = mrow0 + grp;
                float t0 = pA0 + partT[r0]      + bfv;
                float t1 = pB0 + partT[r0 + 8]  + bfv;
                float t2 = pA1 + partT[r0 + 16] + bfv;
                float t3 = pB1 + partT[r0 + 24] + bfv;
                float o0 = 1.f / (1.f + __expf(-t0));
                float o1 = 1.f / (1.f + __expf(-t1));
                float o2 = 1.f / (1.f + __expf(-t2));
                float o3 = 1.f / (1.f + __expf(-t3));
                sts_b8(stateT + (uint32_t)((r0)      * 80 + i), (uint32_t)fp8b(o0));
                sts_b8(stateT + (uint32_t)((r0 + 8)  * 80 + i), (uint32_t)fp8b(o1));
                sts_b8(stateT + (uint32_t)((r0 + 16) * 80 + i), (uint32_t)fp8b(o2));
                sts_b8(stateT + (uint32_t)((r0 + 24) * 80 + i), (uint32_t)fp8b(o3));
                out[(size_t)(tb + r0)      * 64 + i] = o0;   // exact f32 output
                out[(size_t)(tb + r0 + 8)  * 64 + i] = o1;
                out[(size_t)(tb + r0 + 16) * 64 + i] = o2;
                out[(size_t)(tb + r0 + 24) * 64 + i] = o3;
            }
        }
        __syncthreads();                        // step boundary: state + bufs sealed
    }
}

extern "C" void kernel_launch(void* const* d_in, const int* in_sizes, int n_in,
                              void* d_out, int out_size) {
    const float* x   = (const float*)d_in[0];
    const float* z   = (const float*)d_in[1];
    const float* Mg  = (const float*)d_in[2];
    const float* Wi  = (const float*)d_in[3];
    const float* bi  = (const float*)d_in[4];
    const float* Ws1 = (const float*)d_in[5];
    const float* bs1 = (const float*)d_in[6];
    const float* Ws2 = (const float*)d_in[7];
    const float* bs2 = (const float*)d_in[8];
    const float* wf  = (const float*)d_in[9];
    const float* bf  = (const float*)d_in[10];
    float* out = (float*)d_out;

    const int B = in_sizes[0] / 64;              // 65536
    const int grid = B / TILE_M;                 // 512

    cudaFuncSetAttribute(gen_causal_kernel,
                         cudaFuncAttributeMaxDynamicSharedMemorySize, SMEM_TOTAL);
    prep_wi_kernel<<<64, 256>>>(Wi, Mg);
    gen_causal_kernel<<<grid, NTH, SMEM_TOTAL>>>(x, z, bi, Ws1, bs1,
                                                 Ws2, bs2, wf, bf, out);
}